// round 12
// baseline (speedup 1.0000x reference)
#include <cuda_runtime.h>

#define B 8
#define C 512
#define HW 4096
#define TOTAL (B*C*HW)          // 16,777,216
#define TOTAL4 (TOTAL/4)        // 4,194,304
#define GRID1 1184              // 148 SMs x 8 CTAs -> single wave, 2048 thr/SM
#define CHAINB 128              // chain blocks (128 x 8 warps = 1024 warps)
#define READB (GRID1 - CHAINB)  // 1056 streaming-read blocks
#define GRID2 1184

// Scratch (device globals — no allocation allowed)
__device__ float g_text_proj[B*C];
__device__ float g_v_rgb[B*C];
__device__ float g_v_dep[B*C];
__device__ float g_rd[B*2*C];     // per b: [r(512) | d(512)]
__device__ float g_fused[B*C];
__device__ double g_acc[2];       // zero-init; finalize resets after use (replay-safe)
__device__ unsigned int g_count;  // loss finalize counter

// Chain barrier (blocks 0..CHAINB-1): generation counter, monotonic across replays.
__device__ unsigned int g_bar_cnt;
__device__ volatile unsigned int g_bar_gen;

__device__ __forceinline__ void chain_bar() {
    __syncthreads();
    if (threadIdx.x == 0) {
        __threadfence();
        unsigned gen = g_bar_gen;
        if (atomicAdd(&g_bar_cnt, 1u) == CHAINB - 1u) {
            g_bar_cnt = 0;
            __threadfence();
            g_bar_gen = gen + 1u;
        } else {
            while (g_bar_gen == gen) __nanosleep(32);
        }
        __threadfence();
    }
    __syncthreads();
}

__device__ __forceinline__ void pf_l2(const float* p) {
    asm volatile("prefetch.global.L2 [%0];" :: "l"(p));
}

// Warp computes one output channel for all 8 batches; 128 float4 of X per batch in smem.
__device__ __forceinline__ void gemv_acc128(
    const float4* __restrict__ sx4, const float4* __restrict__ w4row,
    float* acc, int lane)
{
#pragma unroll
    for (int i = 0; i < 4; ++i) {
        float4 w = w4row[i * 32 + lane];
#pragma unroll
        for (int b = 0; b < B; ++b) {
            float4 x = sx4[b * 128 + i * 32 + lane];
            acc[b] += w.x * x.x + w.y * x.y + w.z * x.z + w.w * x.w;
        }
    }
}

// xor-reduce: afterwards EVERY lane holds the full sums for all 8 batches.
__device__ __forceinline__ void warp_allreduce(float* acc) {
#pragma unroll
    for (int b = 0; b < B; ++b) {
#pragma unroll
        for (int o = 16; o > 0; o >>= 1)
            acc[b] += __shfl_xor_sync(0xffffffffu, acc[b], o);
    }
}

// K1: chain (blocks 0..127) runs CONCURRENTLY with loss-read (blocks 128..1183).
// No cross-role waits — the chain->write dependency is the K1->K2 kernel boundary.
__global__ void __launch_bounds__(256, 8) k1_chain_loss(
    const float4* __restrict__ rgb, const float4* __restrict__ dep,
    float* __restrict__ out_s,
    const float* __restrict__ text,
    const float* __restrict__ tp_w,   const float* __restrict__ tp_b,
    const float* __restrict__ rgb_wv, const float* __restrict__ rgb_bv,
    const float* __restrict__ dep_wv, const float* __restrict__ dep_bv,
    const float* __restrict__ rgb_wo, const float* __restrict__ rgb_bo,
    const float* __restrict__ dep_wo, const float* __restrict__ dep_bo,
    const float* __restrict__ gate_w, const float* __restrict__ gate_b,
    const float* __restrict__ bn_g,   const float* __restrict__ bn_b)
{
#if __CUDA_ARCH__ >= 900
    if (threadIdx.x == 0) cudaTriggerProgrammaticLaunchCompletion();
#endif
    __shared__ float4 sx4[1024];   // 16KB staging (chain blocks only)
    __shared__ float sh2[8], sh1[8];
    int tid = threadIdx.x;
    int warp = tid >> 5, lane = tid & 31;

    if (blockIdx.x < CHAINB) {
        // ======================= CHAIN ROLE =======================
        int gwarp = blockIdx.x * 8 + warp;     // 0..1023
        bool lower = (gwarp < 512);            // blocks 0..63 are 'lower'

        // L2 prefetch of this warp's stage-2/3/4 weight rows
        {
            const float* s2row = lower ? (rgb_wv + (size_t)gwarp * 512)
                                       : (dep_wv + (size_t)(gwarp - 512) * 512);
            if (lane < 16) pf_l2(s2row + lane * 32);
            const float* s3row = lower ? (rgb_wo + (size_t)gwarp * 512)
                                       : (dep_wo + (size_t)(gwarp - 512) * 512);
            if (lane < 16) pf_l2(s3row + lane * 32);
            if (lower) pf_l2(gate_w + (size_t)gwarp * 1024 + lane * 32);
        }

        // ---- S1: text_proj = text @ tp_w.T + tp_b (blocks 0..63) ----
        if (lower) {
            const float4* X4 = reinterpret_cast<const float4*>(text);
            for (int i = tid; i < 1024; i += 256) sx4[i] = X4[i];
            __syncthreads();
            float acc[B] = {0,0,0,0,0,0,0,0};
            gemv_acc128(sx4, reinterpret_cast<const float4*>(tp_w) + (size_t)gwarp * 128, acc, lane);
            warp_allreduce(acc);
            if (lane == 0) {
                float bv = tp_b[gwarp];
#pragma unroll
                for (int b = 0; b < B; ++b) g_text_proj[b * C + gwarp] = acc[b] + bv;
            }
        }
        chain_bar();

        // ---- S2: v = text_proj @ Wv.T + bv ----
        {
            const float4* X4 = reinterpret_cast<const float4*>(g_text_proj);
            for (int i = tid; i < 1024; i += 256) sx4[i] = X4[i];
            __syncthreads();
            float acc[B] = {0,0,0,0,0,0,0,0};
            if (lower) {
                gemv_acc128(sx4, reinterpret_cast<const float4*>(rgb_wv) + (size_t)gwarp * 128, acc, lane);
                warp_allreduce(acc);
                if (lane == 0) {
                    float bv = rgb_bv[gwarp];
#pragma unroll
                    for (int b = 0; b < B; ++b) g_v_rgb[b * C + gwarp] = acc[b] + bv;
                }
            } else {
                int c = gwarp - 512;
                gemv_acc128(sx4, reinterpret_cast<const float4*>(dep_wv) + (size_t)c * 128, acc, lane);
                warp_allreduce(acc);
                if (lane == 0) {
                    float bv = dep_bv[c];
#pragma unroll
                    for (int b = 0; b < B; ++b) g_v_dep[b * C + c] = acc[b] + bv;
                }
            }
        }
        chain_bar();

        // ---- S3: r/d = v @ Wo.T + bo -> g_rd[b, r|d] ----
        {
            const float4* X4 = reinterpret_cast<const float4*>(lower ? g_v_rgb : g_v_dep);
            for (int i = tid; i < 1024; i += 256) sx4[i] = X4[i];
            __syncthreads();
            float acc[B] = {0,0,0,0,0,0,0,0};
            if (lower) {
                gemv_acc128(sx4, reinterpret_cast<const float4*>(rgb_wo) + (size_t)gwarp * 128, acc, lane);
                warp_allreduce(acc);
                if (lane == 0) {
                    float bv = rgb_bo[gwarp];
#pragma unroll
                    for (int b = 0; b < B; ++b) g_rd[b * 2 * C + gwarp] = acc[b] + bv;
                }
            } else {
                int c = gwarp - 512;
                gemv_acc128(sx4, reinterpret_cast<const float4*>(dep_wo) + (size_t)c * 128, acc, lane);
                warp_allreduce(acc);
                if (lane == 0) {
                    float bv = dep_bo[c];
#pragma unroll
                    for (int b = 0; b < B; ++b) g_rd[b * 2 * C + C + c] = acc[b] + bv;
                }
            }
        }
        chain_bar();

        // ---- S4 + S5 fused (blocks 0..63): gate GEMV (K=1024 in two 16KB passes)
        //      + BN over batch + sigmoid + fuse ----
        if (lower) {
            const float4* rd4 = reinterpret_cast<const float4*>(g_rd);
            float acc[B] = {0,0,0,0,0,0,0,0};
#pragma unroll
            for (int p = 0; p < 2; ++p) {
                __syncthreads();
                for (int i = tid; i < 1024; i += 256)
                    sx4[i] = rd4[(i >> 7) * 256 + p * 128 + (i & 127)];
                __syncthreads();
                gemv_acc128(sx4, reinterpret_cast<const float4*>(gate_w)
                                 + (size_t)gwarp * 256 + p * 128, acc, lane);
            }
            warp_allreduce(acc);        // every lane now has all 8 batch sums

            int c = gwarp;
            float gbias = gate_b[c];
            float p[B];
            float mean = 0.f;
#pragma unroll
            for (int b = 0; b < B; ++b) { p[b] = acc[b] + gbias; mean += p[b]; }
            mean *= (1.f / B);
            float var = 0.f;
#pragma unroll
            for (int b = 0; b < B; ++b) { float d = p[b] - mean; var += d * d; }
            var *= (1.f / B);
            float rstd = rsqrtf(var + 1e-5f);
            float gg = bn_g[c], gb = bn_b[c];
            if (lane < B) {
                int b = lane;
                float xh   = (p[b] - mean) * rstd;
                float gate = 1.f / (1.f + expf(-(gg * xh + gb)));
                float r = g_rd[b * 2 * C + c];
                float d = g_rd[b * 2 * C + C + c];
                g_fused[b * C + c] = gate * r + (1.f - gate) * d;
            }
        }
    } else {
        // ======================= LOSS-READ ROLE =======================
        int t0 = (blockIdx.x - CHAINB) * 256 + tid;
        int stride = READB * 256;
        float s2 = 0.f, s1 = 0.f;
        for (int i = t0; i < TOTAL4; i += stride) {
            float4 r = __ldcs(rgb + i);
            float4 d = __ldcs(dep + i);
            float dx = r.x - d.x, dy = r.y - d.y, dz = r.z - d.z, dw = r.w - d.w;
            s2 += dx*dx + dy*dy + dz*dz + dw*dw;
            s1 += fabsf(dx) + fabsf(dy) + fabsf(dz) + fabsf(dw);
        }
#pragma unroll
        for (int o = 16; o > 0; o >>= 1) {
            s2 += __shfl_down_sync(0xffffffffu, s2, o);
            s1 += __shfl_down_sync(0xffffffffu, s1, o);
        }
        if (lane == 0) { sh2[warp] = s2; sh1[warp] = s1; }
        __syncthreads();
        if (tid == 0) {
            float t2 = 0.f, t1 = 0.f;
#pragma unroll
            for (int j = 0; j < 8; ++j) { t2 += sh2[j]; t1 += sh1[j]; }
            atomicAdd(&g_acc[0], (double)t2);
            atomicAdd(&g_acc[1], (double)t1);
            __threadfence();
            if (atomicAdd(&g_count, 1u) == READB - 1u) {
                g_count = 0;
                const double inv = 1.0 / (double)TOTAL;
                double a0 = atomicAdd(&g_acc[0], 0.0);
                double a1 = atomicAdd(&g_acc[1], 0.0);
                out_s[TOTAL]     = (float)(a0 * inv);   // pixel_loss
                out_s[TOTAL + 1] = (float)(a1 * inv);   // depth_loss
                g_acc[0] = 0.0; g_acc[1] = 0.0;          // reset for next replay
                __threadfence();
            }
        }
    }
}

// K2: broadcast fused over HW (64MB write). PDL secondary; gridsync guarantees
// K1 completion + visibility of g_fused regardless of early launch.
__global__ void __launch_bounds__(256) k2_write(float4* __restrict__ out)
{
#if __CUDA_ARCH__ >= 900
    cudaGridDependencySynchronize();
#endif
    int stride = gridDim.x * blockDim.x;
    for (int i = blockIdx.x * blockDim.x + threadIdx.x; i < TOTAL4; i += stride) {
        float f = g_fused[i >> 10];                 // 1024 float4 per (b,c)
        __stcs(out + i, make_float4(f, f, f, f));
    }
}

extern "C" void kernel_launch(void* const* d_in, const int* in_sizes, int n_in,
                              void* d_out, int out_size)
{
    const float* rgb      = (const float*)d_in[0];
    const float* dep      = (const float*)d_in[1];
    const float* text     = (const float*)d_in[2];
    const float* tp_w     = (const float*)d_in[3];
    const float* tp_b     = (const float*)d_in[4];
    const float* rgb_wqkv = (const float*)d_in[5];
    const float* rgb_bqkv = (const float*)d_in[6];
    const float* rgb_wo   = (const float*)d_in[7];
    const float* rgb_bo   = (const float*)d_in[8];
    const float* dep_wqkv = (const float*)d_in[9];
    const float* dep_bqkv = (const float*)d_in[10];
    const float* dep_wo   = (const float*)d_in[11];
    const float* dep_bo   = (const float*)d_in[12];
    const float* gate_w   = (const float*)d_in[13];
    const float* gate_b   = (const float*)d_in[14];
    const float* bn_g     = (const float*)d_in[15];
    const float* bn_b     = (const float*)d_in[16];
    float* out = (float*)d_out;

    k1_chain_loss<<<GRID1, 256>>>(
        (const float4*)rgb, (const float4*)dep, out,
        text, tp_w, tp_b,
        rgb_wqkv + 2*C*C, rgb_bqkv + 2*C,
        dep_wqkv + 2*C*C, dep_bqkv + 2*C,
        rgb_wo, rgb_bo, dep_wo, dep_bo,
        gate_w, gate_b, bn_g, bn_b);

    // K2 with PDL (launch-latency hiding; correctness via gridsync inside).
    cudaLaunchConfig_t cfg = {};
    cfg.gridDim  = dim3(GRID2);
    cfg.blockDim = dim3(256);
    cfg.dynamicSmemBytes = 0;
    cfg.stream = 0;
    cudaLaunchAttribute attr[1];
    attr[0].id = cudaLaunchAttributeProgrammaticStreamSerialization;
    attr[0].val.programmaticStreamSerializationAllowed = 1;
    cfg.attrs = attr;
    cfg.numAttrs = 1;
    cudaLaunchKernelEx(&cfg, k2_write, (float4*)out);
}

// round 13
// speedup vs baseline: 1.0735x; 1.0735x over previous
#include <cuda_runtime.h>

#define B 8
#define C 512
#define HW 4096
#define TOTAL (B*C*HW)          // 16,777,216
#define TOTAL4 (TOTAL/4)        // 4,194,304
#define PRO4  (TOTAL4/4)        // prologue: first 25% of loss reads overlap the chain
#define CG 64                   // chain grid (64 CTAs x 512 thr = 1024 warps)
#define CT 512
#define NWARP 16
#define LGRID 1184              // fuse grid: 148 SMs x 8 CTAs

// Scratch (device globals — no allocation allowed)
__device__ float g_text_proj[B*C];
__device__ float g_v_rgb[B*C];
__device__ float g_v_dep[B*C];
__device__ float g_rd[B*2*C];     // per b: [r(512) | d(512)]
__device__ float g_fused[B*C];
__device__ double g_acc[2];       // zero-init; finalize resets after use (replay-safe)
__device__ unsigned int g_count;  // loss finalize counter

// Chain barrier: generation counter, monotonic across graph replays.
__device__ unsigned int g_bar_cnt;
__device__ volatile unsigned int g_bar_gen;

__device__ __forceinline__ void chain_bar() {
    __syncthreads();
    if (threadIdx.x == 0) {
        __threadfence();
        unsigned gen = g_bar_gen;
        if (atomicAdd(&g_bar_cnt, 1u) == CG - 1u) {
            g_bar_cnt = 0;
            __threadfence();
            g_bar_gen = gen + 1u;
        } else {
            while (g_bar_gen == gen) __nanosleep(32);
        }
        __threadfence();
    }
    __syncthreads();
}

__device__ __forceinline__ void pf_l2(const float* p) {
    asm volatile("prefetch.global.L2 [%0];" :: "l"(p));
}

template<int K4>
__device__ __forceinline__ void gemv_acc(
    const float4* __restrict__ sx4, const float4* __restrict__ w4row,
    float* acc, int lane)
{
#pragma unroll
    for (int i = 0; i < K4 / 32; ++i) {
        float4 w = w4row[i * 32 + lane];
#pragma unroll
        for (int b = 0; b < B; ++b) {
            float4 x = sx4[b * K4 + i * 32 + lane];
            acc[b] += w.x * x.x + w.y * x.y + w.z * x.z + w.w * x.w;
        }
    }
}

// xor-reduce: afterwards EVERY lane holds the full sums for all 8 batches.
__device__ __forceinline__ void warp_allreduce(float* acc) {
#pragma unroll
    for (int b = 0; b < B; ++b) {
#pragma unroll
        for (int o = 16; o > 0; o >>= 1)
            acc[b] += __shfl_xor_sync(0xffffffffu, acc[b], o);
    }
}

// GEMV chain + BN/gate/fuse: 64 CTAs x 512 threads, 3 grid barriers.
__global__ void __launch_bounds__(CT) chain_kernel(
    const float* __restrict__ text,
    const float* __restrict__ tp_w,   const float* __restrict__ tp_b,
    const float* __restrict__ rgb_wv, const float* __restrict__ rgb_bv,
    const float* __restrict__ dep_wv, const float* __restrict__ dep_bv,
    const float* __restrict__ rgb_wo, const float* __restrict__ rgb_bo,
    const float* __restrict__ dep_wo, const float* __restrict__ dep_bo,
    const float* __restrict__ gate_w, const float* __restrict__ gate_b,
    const float* __restrict__ bn_g,   const float* __restrict__ bn_b)
{
#if __CUDA_ARCH__ >= 900
    // ALL threads trigger -> secondary launches immediately (R11 called it from
    // one thread only, which silently degrades to trigger-at-exit).
    cudaTriggerProgrammaticLaunchCompletion();
#endif
    __shared__ float4 sx4[2048];   // 32KB staging (S4 needs full 8x1024)
    int tid = threadIdx.x;
    int warp = tid >> 5, lane = tid & 31;
    int gwarp = blockIdx.x * NWARP + warp;     // 0..1023
    bool lower = (gwarp < 512);

    // ---- L2 prefetch of this warp's stage-2/3/4 weight rows ----
    {
        const float* s2row = lower ? (rgb_wv + (size_t)gwarp * 512)
                                   : (dep_wv + (size_t)(gwarp - 512) * 512);
        if (lane < 16) pf_l2(s2row + lane * 32);
        const float* s3row = lower ? (rgb_wo + (size_t)gwarp * 512)
                                   : (dep_wo + (size_t)(gwarp - 512) * 512);
        if (lane < 16) pf_l2(s3row + lane * 32);
        if (lower) pf_l2(gate_w + (size_t)gwarp * 1024 + lane * 32);
    }

    // ---- S1: text_proj = text @ tp_w.T + tp_b ----
    if (lower) {
        const float4* X4 = reinterpret_cast<const float4*>(text);
        for (int i = tid; i < 1024; i += CT) sx4[i] = X4[i];
        __syncthreads();
        float acc[B] = {0,0,0,0,0,0,0,0};
        gemv_acc<128>(sx4, reinterpret_cast<const float4*>(tp_w) + (size_t)gwarp * 128, acc, lane);
        warp_allreduce(acc);
        if (lane == 0) {
            float bv = tp_b[gwarp];
#pragma unroll
            for (int b = 0; b < B; ++b) g_text_proj[b * C + gwarp] = acc[b] + bv;
        }
    }
    chain_bar();

    // ---- S2: v = text_proj @ Wv.T + bv ----
    {
        const float4* X4 = reinterpret_cast<const float4*>(g_text_proj);
        for (int i = tid; i < 1024; i += CT) sx4[i] = X4[i];
        __syncthreads();
        float acc[B] = {0,0,0,0,0,0,0,0};
        if (lower) {
            gemv_acc<128>(sx4, reinterpret_cast<const float4*>(rgb_wv) + (size_t)gwarp * 128, acc, lane);
            warp_allreduce(acc);
            if (lane == 0) {
                float bv = rgb_bv[gwarp];
#pragma unroll
                for (int b = 0; b < B; ++b) g_v_rgb[b * C + gwarp] = acc[b] + bv;
            }
        } else {
            int c = gwarp - 512;
            gemv_acc<128>(sx4, reinterpret_cast<const float4*>(dep_wv) + (size_t)c * 128, acc, lane);
            warp_allreduce(acc);
            if (lane == 0) {
                float bv = dep_bv[c];
#pragma unroll
                for (int b = 0; b < B; ++b) g_v_dep[b * C + c] = acc[b] + bv;
            }
        }
    }
    chain_bar();

    // ---- S3: r/d = v @ Wo.T + bo -> g_rd[b, r|d] ----
    {
        const float4* X4 = reinterpret_cast<const float4*>(lower ? g_v_rgb : g_v_dep);
        for (int i = tid; i < 1024; i += CT) sx4[i] = X4[i];
        __syncthreads();
        float acc[B] = {0,0,0,0,0,0,0,0};
        if (lower) {
            gemv_acc<128>(sx4, reinterpret_cast<const float4*>(rgb_wo) + (size_t)gwarp * 128, acc, lane);
            warp_allreduce(acc);
            if (lane == 0) {
                float bv = rgb_bo[gwarp];
#pragma unroll
                for (int b = 0; b < B; ++b) g_rd[b * 2 * C + gwarp] = acc[b] + bv;
            }
        } else {
            int c = gwarp - 512;
            gemv_acc<128>(sx4, reinterpret_cast<const float4*>(dep_wo) + (size_t)c * 128, acc, lane);
            warp_allreduce(acc);
            if (lane == 0) {
                float bv = dep_bo[c];
#pragma unroll
                for (int b = 0; b < B; ++b) g_rd[b * 2 * C + C + c] = acc[b] + bv;
            }
        }
    }
    chain_bar();

    // ---- S4 + S5 fused: gate GEMV (K=1024) + BN over batch + sigmoid + fuse ----
    if (lower) {
        const float4* X4 = reinterpret_cast<const float4*>(g_rd);
        for (int i = tid; i < 2048; i += CT) sx4[i] = X4[i];
        __syncthreads();
        float acc[B] = {0,0,0,0,0,0,0,0};
        gemv_acc<256>(sx4, reinterpret_cast<const float4*>(gate_w) + (size_t)gwarp * 256, acc, lane);
        warp_allreduce(acc);        // every lane now has all 8 batch sums

        int c = gwarp;
        float gbias = gate_b[c];
        float p[B];
        float mean = 0.f;
#pragma unroll
        for (int b = 0; b < B; ++b) { p[b] = acc[b] + gbias; mean += p[b]; }
        mean *= (1.f / B);
        float var = 0.f;
#pragma unroll
        for (int b = 0; b < B; ++b) { float d = p[b] - mean; var += d * d; }
        var *= (1.f / B);
        float rstd = rsqrtf(var + 1e-5f);
        float gg = bn_g[c], gb = bn_b[c];
        if (lane < B) {
            int b = lane;
            float xh   = (p[b] - mean) * rstd;
            float gate = 1.f / (1.f + expf(-(gg * xh + gb)));
            float r = g_rd[b * 2 * C + c];
            float d = g_rd[b * 2 * C + C + c];
            g_fused[b * C + c] = gate * r + (1.f - gate) * d;
        }
    }
}

// PDL secondary. Prologue: read first 25% of loss data (overlaps chain).
// Then gridsync (chain done + visible), then R10-style interleaved loop:
// write all 64MB of out while reading the remaining 75% of rgb/dep.
__global__ void __launch_bounds__(256) fuse_loss_kernel(
    const float4* __restrict__ rgb, const float4* __restrict__ dep,
    float4* __restrict__ out, float* __restrict__ out_s)
{
    int tid = threadIdx.x;
    int stride = gridDim.x * blockDim.x;
    int t0 = blockIdx.x * blockDim.x + tid;
    float s2 = 0.f, s1 = 0.f;

    // ---- Prologue: bounded overlap with the chain ----
    for (int i = t0; i < PRO4; i += stride) {
        float4 r = __ldcs(rgb + i);
        float4 d = __ldcs(dep + i);
        float dx = r.x - d.x, dy = r.y - d.y, dz = r.z - d.z, dw = r.w - d.w;
        s2 += dx*dx + dy*dy + dz*dz + dw*dw;
        s1 += fabsf(dx) + fabsf(dy) + fabsf(dz) + fabsf(dw);
    }

#if __CUDA_ARCH__ >= 900
    cudaGridDependencySynchronize();   // chain complete + g_fused visible
#endif

    // ---- Main: interleaved remaining reads + full broadcast write ----
    for (int i = t0; i < TOTAL4; i += stride) {
        if (i >= PRO4) {
            float4 r = __ldcs(rgb + i);
            float4 d = __ldcs(dep + i);
            float dx = r.x - d.x, dy = r.y - d.y, dz = r.z - d.z, dw = r.w - d.w;
            s2 += dx*dx + dy*dy + dz*dz + dw*dw;
            s1 += fabsf(dx) + fabsf(dy) + fabsf(dz) + fabsf(dw);
        }
        float f = g_fused[i >> 10];                 // 1024 float4 per (b,c)
        __stcs(out + i, make_float4(f, f, f, f));
    }

    // ---- Loss reduce + finalize ----
#pragma unroll
    for (int o = 16; o > 0; o >>= 1) {
        s2 += __shfl_down_sync(0xffffffffu, s2, o);
        s1 += __shfl_down_sync(0xffffffffu, s1, o);
    }
    __shared__ float sh2[8], sh1[8];
    int w = tid >> 5, l = tid & 31;
    if (l == 0) { sh2[w] = s2; sh1[w] = s1; }
    __syncthreads();
    if (tid == 0) {
        float t2 = 0.f, t1 = 0.f;
#pragma unroll
        for (int j = 0; j < 8; ++j) { t2 += sh2[j]; t1 += sh1[j]; }
        atomicAdd(&g_acc[0], (double)t2);
        atomicAdd(&g_acc[1], (double)t1);
        __threadfence();
        if (atomicAdd(&g_count, 1u) == gridDim.x - 1u) {
            g_count = 0;
            const double inv = 1.0 / (double)TOTAL;
            double a0 = atomicAdd(&g_acc[0], 0.0);
            double a1 = atomicAdd(&g_acc[1], 0.0);
            out_s[TOTAL]     = (float)(a0 * inv);   // pixel_loss
            out_s[TOTAL + 1] = (float)(a1 * inv);   // depth_loss
            g_acc[0] = 0.0; g_acc[1] = 0.0;          // reset for next replay
            __threadfence();
        }
    }
}

extern "C" void kernel_launch(void* const* d_in, const int* in_sizes, int n_in,
                              void* d_out, int out_size)
{
    const float* rgb      = (const float*)d_in[0];
    const float* dep      = (const float*)d_in[1];
    const float* text     = (const float*)d_in[2];
    const float* tp_w     = (const float*)d_in[3];
    const float* tp_b     = (const float*)d_in[4];
    const float* rgb_wqkv = (const float*)d_in[5];
    const float* rgb_bqkv = (const float*)d_in[6];
    const float* rgb_wo   = (const float*)d_in[7];
    const float* rgb_bo   = (const float*)d_in[8];
    const float* dep_wqkv = (const float*)d_in[9];
    const float* dep_bqkv = (const float*)d_in[10];
    const float* dep_wo   = (const float*)d_in[11];
    const float* dep_bo   = (const float*)d_in[12];
    const float* gate_w   = (const float*)d_in[13];
    const float* gate_b   = (const float*)d_in[14];
    const float* bn_g     = (const float*)d_in[15];
    const float* bn_b     = (const float*)d_in[16];
    float* out = (float*)d_out;

    chain_kernel<<<CG, CT>>>(
        text, tp_w, tp_b,
        rgb_wqkv + 2*C*C, rgb_bqkv + 2*C,
        dep_wqkv + 2*C*C, dep_bqkv + 2*C,
        rgb_wo, rgb_bo, dep_wo, dep_bo,
        gate_w, gate_b, bn_g, bn_b);

    cudaLaunchConfig_t cfg = {};
    cfg.gridDim  = dim3(LGRID);
    cfg.blockDim = dim3(256);
    cfg.dynamicSmemBytes = 0;
    cfg.stream = 0;
    cudaLaunchAttribute attr[1];
    attr[0].id = cudaLaunchAttributeProgrammaticStreamSerialization;
    attr[0].val.programmaticStreamSerializationAllowed = 1;
    cfg.attrs = attr;
    cfg.numAttrs = 1;
    cudaLaunchKernelEx(&cfg, fuse_loss_kernel,
                       (const float4*)rgb, (const float4*)dep, (float4*)out, out);
}